// round 5
// baseline (speedup 1.0000x reference)
#include <cuda_runtime.h>
#include <cuda_bf16.h>
#include <cstdint>

#define Bsz 256
#define Ssz 256
#define Esz 256
#define Hsz 1024
#define G4  4096   // 4*H

// ---- step kernel tiling ----
#define BMt 64                  // M tile (batch rows per CTA)
#define HT  32                  // h columns per gate per CTA
#define NT  128                 // N tile = 4 gates * HT
#define KC  64                  // K chunk (bf16 elements = 128 B row)
#define NCHUNK (Hsz / KC)       // 16
#define NSTAGE 3

// ---- smem layout ----
#define A_MAT_BYTES (BMt * KC * 2)                      // 8 KB per matrix
#define B_MAT_BYTES (NT * KC * 2)                       // 16 KB per matrix
#define STAGE_BYTES (2 * A_MAT_BYTES + 2 * B_MAT_BYTES) // 48 KB
#define OFF_AHI 0
#define OFF_ALO (A_MAT_BYTES)
#define OFF_BHI (2 * A_MAT_BYTES)
#define OFF_BLO (2 * A_MAT_BYTES + B_MAT_BYTES)
#define SMEM_TOTAL (NSTAGE * STAGE_BYTES)               // 144 KB
#define DPITCH 132

// ---- device globals (no allocation allowed) ----
__device__ float g_letter_proj[30 * G4];
__device__ float g_state_proj[4 * G4];
__device__ __nv_bfloat16 g_W_hi[(size_t)G4 * Hsz];   // 8 MB
__device__ __nv_bfloat16 g_W_lo[(size_t)G4 * Hsz];   // 8 MB
__device__ __nv_bfloat16 g_h_hi[2][Bsz * Hsz];
__device__ __nv_bfloat16 g_h_lo[2][Bsz * Hsz];

// ---------------------------------------------------------------------------
// PTX helpers (sm_80-era instructions only)
// ---------------------------------------------------------------------------
__device__ __forceinline__ uint32_t smem_u32(const void* p) {
    uint32_t a;
    asm("{ .reg .u64 t; cvta.to.shared.u64 t, %1; cvt.u32.u64 %0, t; }"
        : "=r"(a) : "l"(p));
    return a;
}
__device__ __forceinline__ void cp16(uint32_t s, const void* g) {
    asm volatile("cp.async.cg.shared.global [%0], [%1], 16;"
                 :: "r"(s), "l"(g) : "memory");
}
#define CP_COMMIT() asm volatile("cp.async.commit_group;" ::: "memory")
#define CP_WAIT1()  asm volatile("cp.async.wait_group 1;" ::: "memory")

__device__ __forceinline__ void ldsm4(uint32_t a, uint32_t* r) {
    asm volatile("ldmatrix.sync.aligned.m8n8.x4.shared.b16 {%0,%1,%2,%3}, [%4];"
                 : "=r"(r[0]), "=r"(r[1]), "=r"(r[2]), "=r"(r[3]) : "r"(a));
}
__device__ __forceinline__ void mma16816(float* c, const uint32_t* a,
                                         const uint32_t* b) {
    asm volatile(
        "mma.sync.aligned.m16n8k16.row.col.f32.bf16.bf16.f32 "
        "{%0,%1,%2,%3}, {%4,%5,%6,%7}, {%8,%9}, {%0,%1,%2,%3};"
        : "+f"(c[0]), "+f"(c[1]), "+f"(c[2]), "+f"(c[3])
        : "r"(a[0]), "r"(a[1]), "r"(a[2]), "r"(a[3]), "r"(b[0]), "r"(b[1]));
}
__device__ __forceinline__ float sigmoidf_(float x) {
    return 1.0f / (1.0f + expf(-x));
}

// ---------------------------------------------------------------------------
// One-time prep: split W_hh into bf16 hi/lo
// ---------------------------------------------------------------------------
__global__ void wsplit_kernel(const float* __restrict__ W) {
    size_t i = ((size_t)blockIdx.x * blockDim.x + threadIdx.x) * 4;
    float4 w = *(const float4*)(W + i);
    float v[4] = {w.x, w.y, w.z, w.w};
    #pragma unroll
    for (int j = 0; j < 4; j++) {
        __nv_bfloat16 hi = __float2bfloat16(v[j]);
        g_W_hi[i + j] = hi;
        g_W_lo[i + j] = __float2bfloat16(v[j] - __bfloat162float(hi));
    }
}

// ---------------------------------------------------------------------------
// One-time prep: x_proj lookup tables (incl. biases)
// ---------------------------------------------------------------------------
__global__ void proj_kernel(const float* __restrict__ letter_emb,
                            const float* __restrict__ state_emb,
                            const float* __restrict__ W_ih,
                            const float* __restrict__ b_ih,
                            const float* __restrict__ b_hh) {
    int tok  = blockIdx.y;
    int g    = blockIdx.x * 8 + (threadIdx.x >> 5);
    int lane = threadIdx.x & 31;

    const float* emb;
    const float* w;
    if (tok < 30) {
        emb = letter_emb + tok * Esz;
        w   = W_ih + (size_t)g * (2 * Esz);
    } else {
        emb = state_emb + (tok - 30) * Esz;
        w   = W_ih + (size_t)g * (2 * Esz) + Esz;
    }

    float acc = 0.f;
    for (int k = lane; k < Esz; k += 32)
        acc += emb[k] * w[k];
    #pragma unroll
    for (int off = 16; off; off >>= 1)
        acc += __shfl_xor_sync(0xFFFFFFFFu, acc, off);

    if (lane == 0) {
        if (tok < 30)
            g_letter_proj[tok * G4 + g] = acc + b_ih[g] + b_hh[g];
        else
            g_state_proj[(tok - 30) * G4 + g] = acc;
    }
}

// ---------------------------------------------------------------------------
// HMMA LSTM step. grid (32, 4) = 128 CTAs, 512 threads (16 warps, 4x4).
// Warp tile M16 x N32. D = Ahi*Bhi + Alo*Bhi + Ahi*Blo (fp32 accum).
// ---------------------------------------------------------------------------
__global__ void __launch_bounds__(512, 1)
lstm_step_mma(const int* __restrict__ letter_seq,
              const int* __restrict__ state_seq,
              float* __restrict__ out_h,
              float* __restrict__ out_c,
              int s) {
    extern __shared__ char smem[];
    const uint32_t smem_base = smem_u32(smem);

    const int tid = threadIdx.x;
    const int h0  = blockIdx.x * HT;
    const int bm0 = blockIdx.y * BMt;
    const int rbuf = (s & 1) ^ 1;
    const int wbuf = s & 1;

    const int wid = tid >> 5;
    const int l   = tid & 31;
    const int wm  = wid >> 2;         // 0..3 (M)
    const int wn  = wid & 3;          // 0..3 (N)

    // acc[4] quads: nq = x*2 + half  (n8 frags across warp's 32 cols)
    float acc[4][4];
    #pragma unroll
    for (int j = 0; j < 4; j++)
        #pragma unroll
        for (int k = 0; k < 4; k++)
            acc[j][k] = 0.f;

    if (s > 0) {
        // ---- stage-load constants ----
        const int r  = tid >> 3;                 // 0..63
        const int gq = tid & 7;                  // 16B granule in 128B row
        const uint32_t swA = (uint32_t)((gq ^ (r & 7)) * 16);
        const __nv_bfloat16* hh = g_h_hi[rbuf] + (size_t)(bm0 + r) * Hsz + gq * 8;
        const __nv_bfloat16* hl = g_h_lo[rbuf] + (size_t)(bm0 + r) * Hsz + gq * 8;
        // B rows n = r and r+64; n -> W row (n>>5)*H + h0 + (n&31)
        const size_t wrow0 = (size_t)((r >> 5) * Hsz + h0 + (r & 31)) * Hsz + gq * 8;
        const int n1 = r + 64;
        const size_t wrow1 = (size_t)((n1 >> 5) * Hsz + h0 + (n1 & 31)) * Hsz + gq * 8;
        const uint32_t swB1 = (uint32_t)((gq ^ (n1 & 7)) * 16);

        auto load_stage = [&](int ch) {
            const int k0 = ch * KC;
            const uint32_t sb = smem_base + (uint32_t)(ch % NSTAGE) * STAGE_BYTES;
            cp16(sb + OFF_AHI + r * 128 + swA, hh + k0);
            cp16(sb + OFF_ALO + r * 128 + swA, hl + k0);
            cp16(sb + OFF_BHI + r * 128 + swA,  g_W_hi + wrow0 + k0);
            cp16(sb + OFF_BLO + r * 128 + swA,  g_W_lo + wrow0 + k0);
            cp16(sb + OFF_BHI + n1 * 128 + swB1, g_W_hi + wrow1 + k0);
            cp16(sb + OFF_BLO + n1 * 128 + swB1, g_W_lo + wrow1 + k0);
        };

        // ---- ldmatrix lane constants ----
        const int a_r0  = wm * 16 + (l & 7) + ((l >> 3) & 1) * 8;
        const int a_kh  = l >> 4;
        const int a_swr = a_r0 & 7;
        const int b_n0  = wn * 32 + (l & 7) + (l >> 4) * 8;   // +16 for x=1
        const int b_kh  = (l >> 3) & 1;

        load_stage(0); CP_COMMIT();
        load_stage(1); CP_COMMIT();

        for (int ch = 0; ch < NCHUNK; ch++) {
            CP_WAIT1();
            __syncthreads();
            if (ch + 2 < NCHUNK) load_stage(ch + 2);
            CP_COMMIT();

            const uint32_t sb = smem_base + (uint32_t)(ch % NSTAGE) * STAGE_BYTES;
            #pragma unroll
            for (int ks = 0; ks < 4; ks++) {
                const int agq = ks * 2 + a_kh;
                const int bgq = ks * 2 + b_kh;
                uint32_t ah[4], al[4], bh[2][4], bl[2][4];
                {
                    uint32_t arow = (uint32_t)a_r0 * 128
                                  + (uint32_t)((agq ^ a_swr) * 16);
                    ldsm4(sb + OFF_AHI + arow, ah);
                    ldsm4(sb + OFF_ALO + arow, al);
                }
                #pragma unroll
                for (int x = 0; x < 2; x++) {
                    int bn = b_n0 + x * 16;
                    uint32_t brow = (uint32_t)bn * 128
                                  + (uint32_t)((bgq ^ (bn & 7)) * 16);
                    ldsm4(sb + OFF_BHI + brow, bh[x]);
                    ldsm4(sb + OFF_BLO + brow, bl[x]);
                }
                // term-major: reuse distance 4 between MMAs into same quad
                #pragma unroll
                for (int x = 0; x < 2; x++) {
                    mma16816(acc[x * 2],     ah, &bh[x][0]);
                    mma16816(acc[x * 2 + 1], ah, &bh[x][2]);
                }
                #pragma unroll
                for (int x = 0; x < 2; x++) {
                    mma16816(acc[x * 2],     al, &bh[x][0]);
                    mma16816(acc[x * 2 + 1], al, &bh[x][2]);
                }
                #pragma unroll
                for (int x = 0; x < 2; x++) {
                    mma16816(acc[x * 2],     ah, &bl[x][0]);
                    mma16816(acc[x * 2 + 1], ah, &bl[x][2]);
                }
            }
        }

        // ---- dump accums to smem D[64][DPITCH] ----
        __syncthreads();
        float* Dsm = (float*)smem;
        #pragma unroll
        for (int nq = 0; nq < 4; nq++) {
            int m = wm * 16 + (l >> 2);
            int n = wn * 32 + nq * 8 + (l & 3) * 2;
            *(float2*)&Dsm[m * DPITCH + n] = make_float2(acc[nq][0], acc[nq][1]);
            *(float2*)&Dsm[(m + 8) * DPITCH + n] = make_float2(acc[nq][2], acc[nq][3]);
        }
        __syncthreads();
    }

    // ---- fused LSTM cell epilogue: thread -> (m, 4 h-cols) ----
    {
        const float* Dsm = (const float*)smem;
        const int m  = tid >> 3;          // 0..63
        const int hq = tid & 7;           // 4-col group
        const int b  = bm0 + m;
        const int lt = letter_seq[b * Ssz + s];
        const int st = state_seq[b * Ssz + s];
        const float* lp = g_letter_proj + (size_t)lt * G4 + h0;
        const float* sp = g_state_proj  + (size_t)st * G4 + h0;
        const size_t base = (size_t)b * (Ssz * Hsz) + (size_t)s * Hsz + h0;
        const int hl0 = hq * 4;

        float hv[4], cv[4];
        #pragma unroll
        for (int j = 0; j < 4; j++) {
            const int hlc = hl0 + j;
            float pi, pf, pg, po;
            if (s > 0) {
                pi = Dsm[m * DPITCH + 0 * 32 + hlc];
                pf = Dsm[m * DPITCH + 1 * 32 + hlc];
                pg = Dsm[m * DPITCH + 2 * 32 + hlc];
                po = Dsm[m * DPITCH + 3 * 32 + hlc];
            } else {
                pi = pf = pg = po = 0.f;
            }
            pi += lp[hlc]           + sp[hlc];
            pf += lp[Hsz + hlc]     + sp[Hsz + hlc];
            pg += lp[2 * Hsz + hlc] + sp[2 * Hsz + hlc];
            po += lp[3 * Hsz + hlc] + sp[3 * Hsz + hlc];
            float cprev = (s > 0) ? out_c[base - Hsz + hlc] : 0.f;
            float c = sigmoidf_(pf) * cprev + sigmoidf_(pi) * tanhf(pg);
            cv[j] = c;
            hv[j] = sigmoidf_(po) * tanhf(c);
        }
        *(float4*)(out_h + base + hl0) = make_float4(hv[0], hv[1], hv[2], hv[3]);
        *(float4*)(out_c + base + hl0) = make_float4(cv[0], cv[1], cv[2], cv[3]);

        __nv_bfloat162 dh[2], dl[2];
        #pragma unroll
        for (int j = 0; j < 2; j++) {
            float x0 = hv[2 * j], x1 = hv[2 * j + 1];
            __nv_bfloat16 b0 = __float2bfloat16(x0);
            __nv_bfloat16 b1 = __float2bfloat16(x1);
            dh[j] = __nv_bfloat162(b0, b1);
            dl[j] = __nv_bfloat162(__float2bfloat16(x0 - __bfloat162float(b0)),
                                   __float2bfloat16(x1 - __bfloat162float(b1)));
        }
        *(uint2*)(g_h_hi[wbuf] + (size_t)b * Hsz + h0 + hl0) = *(const uint2*)dh;
        *(uint2*)(g_h_lo[wbuf] + (size_t)b * Hsz + h0 + hl0) = *(const uint2*)dl;
    }
}

// ---------------------------------------------------------------------------
extern "C" void kernel_launch(void* const* d_in, const int* in_sizes, int n_in,
                              void* d_out, int out_size) {
    const int*   letter_seq = (const int*)d_in[0];
    const int*   state_seq  = (const int*)d_in[1];
    const float* letter_emb = (const float*)d_in[2];
    const float* state_emb  = (const float*)d_in[3];
    const float* W_ih       = (const float*)d_in[4];
    const float* W_hh       = (const float*)d_in[5];
    const float* b_ih       = (const float*)d_in[6];
    const float* b_hh       = (const float*)d_in[7];

    float* out_h = (float*)d_out;
    float* out_c = out_h + (size_t)Bsz * Ssz * Hsz;

    static int smem_set = 0;
    if (!smem_set) {
        cudaFuncSetAttribute(lstm_step_mma,
                             cudaFuncAttributeMaxDynamicSharedMemorySize,
                             SMEM_TOTAL);
        smem_set = 1;
    }

    wsplit_kernel<<<(G4 * Hsz) / (256 * 4), 256>>>(W_hh);
    proj_kernel<<<dim3(G4 / 8, 34), 256>>>(letter_emb, state_emb, W_ih, b_ih, b_hh);

    for (int s = 0; s < Ssz; s++) {
        lstm_step_mma<<<dim3(Hsz / HT, Bsz / BMt), 512, SMEM_TOTAL>>>(
            letter_seq, state_seq, out_h, out_c, s);
    }
}

// round 6
// speedup vs baseline: 1.0178x; 1.0178x over previous
#include <cuda_runtime.h>
#include <cuda_bf16.h>
#include <cstdint>

#define Bsz 256
#define Ssz 256
#define Esz 256
#define Hsz 1024
#define G4  4096   // 4*H

// ---- step kernel tiling (R4 layout: 8 warps, warp tile M32xN32) ----
#define BMt 64                  // M tile (batch rows per CTA)
#define HT  32                  // h columns per gate per CTA
#define NT  128                 // N tile = 4 gates * HT
#define KC  64                  // K chunk (bf16 elements = 128 B row)
#define NCHUNK (Hsz / KC)       // 16
#define NSTAGE 3

// ---- smem layout ----
#define A_MAT_BYTES (BMt * KC * 2)                      // 8 KB per matrix
#define B_MAT_BYTES (NT * KC * 2)                       // 16 KB per matrix
#define STAGE_BYTES (2 * A_MAT_BYTES + 2 * B_MAT_BYTES) // 48 KB
#define OFF_AHI 0
#define OFF_ALO (A_MAT_BYTES)
#define OFF_BHI (2 * A_MAT_BYTES)
#define OFF_BLO (2 * A_MAT_BYTES + B_MAT_BYTES)
#define SMEM_TOTAL (NSTAGE * STAGE_BYTES)               // 144 KB
#define DPITCH 132

// ---- device globals (no allocation allowed) ----
__device__ float g_letter_proj[30 * G4];
__device__ float g_state_proj[4 * G4];
__device__ __nv_bfloat16 g_W_hi[(size_t)G4 * Hsz];   // 8 MB
__device__ __nv_bfloat16 g_W_lo[(size_t)G4 * Hsz];   // 8 MB
__device__ __nv_bfloat16 g_h_hi[2][Bsz * Hsz];       // ping-pong h (bf16 hi)
__device__ __nv_bfloat16 g_h_lo[2][Bsz * Hsz];       // ping-pong h (bf16 lo)
__device__ float g_c[2][Bsz * Hsz];                  // ping-pong c (fp32, L2-resident)

// ---------------------------------------------------------------------------
// PTX helpers
// ---------------------------------------------------------------------------
__device__ __forceinline__ uint32_t smem_u32(const void* p) {
    uint32_t a;
    asm("{ .reg .u64 t; cvta.to.shared.u64 t, %1; cvt.u32.u64 %0, t; }"
        : "=r"(a) : "l"(p));
    return a;
}
__device__ __forceinline__ void cp16(uint32_t s, const void* g) {
    asm volatile("cp.async.cg.shared.global [%0], [%1], 16;"
                 :: "r"(s), "l"(g) : "memory");
}
#define CP_COMMIT() asm volatile("cp.async.commit_group;" ::: "memory")
#define CP_WAIT1()  asm volatile("cp.async.wait_group 1;" ::: "memory")

__device__ __forceinline__ void ldsm4(uint32_t a, uint32_t* r) {
    asm volatile("ldmatrix.sync.aligned.m8n8.x4.shared.b16 {%0,%1,%2,%3}, [%4];"
                 : "=r"(r[0]), "=r"(r[1]), "=r"(r[2]), "=r"(r[3]) : "r"(a));
}
__device__ __forceinline__ void mma16816(float* c, const uint32_t* a,
                                         const uint32_t* b) {
    asm volatile(
        "mma.sync.aligned.m16n8k16.row.col.f32.bf16.bf16.f32 "
        "{%0,%1,%2,%3}, {%4,%5,%6,%7}, {%8,%9}, {%0,%1,%2,%3};"
        : "+f"(c[0]), "+f"(c[1]), "+f"(c[2]), "+f"(c[3])
        : "r"(a[0]), "r"(a[1]), "r"(a[2]), "r"(a[3]), "r"(b[0]), "r"(b[1]));
}
// streaming store (evict-first): output-only data must not evict W from L2
__device__ __forceinline__ void stcs4(float* p, float4 v) {
    asm volatile("st.global.cs.v4.f32 [%0], {%1,%2,%3,%4};"
                 :: "l"(p), "f"(v.x), "f"(v.y), "f"(v.z), "f"(v.w) : "memory");
}
__device__ __forceinline__ float sigmoidf_(float x) {
    return 1.0f / (1.0f + expf(-x));
}

// ---------------------------------------------------------------------------
// One-time prep: split W_hh into bf16 hi/lo
// ---------------------------------------------------------------------------
__global__ void wsplit_kernel(const float* __restrict__ W) {
    size_t i = ((size_t)blockIdx.x * blockDim.x + threadIdx.x) * 4;
    float4 w = *(const float4*)(W + i);
    float v[4] = {w.x, w.y, w.z, w.w};
    #pragma unroll
    for (int j = 0; j < 4; j++) {
        __nv_bfloat16 hi = __float2bfloat16(v[j]);
        g_W_hi[i + j] = hi;
        g_W_lo[i + j] = __float2bfloat16(v[j] - __bfloat162float(hi));
    }
}

// ---------------------------------------------------------------------------
// One-time prep: x_proj lookup tables (incl. biases)
// ---------------------------------------------------------------------------
__global__ void proj_kernel(const float* __restrict__ letter_emb,
                            const float* __restrict__ state_emb,
                            const float* __restrict__ W_ih,
                            const float* __restrict__ b_ih,
                            const float* __restrict__ b_hh) {
    int tok  = blockIdx.y;
    int g    = blockIdx.x * 8 + (threadIdx.x >> 5);
    int lane = threadIdx.x & 31;

    const float* emb;
    const float* w;
    if (tok < 30) {
        emb = letter_emb + tok * Esz;
        w   = W_ih + (size_t)g * (2 * Esz);
    } else {
        emb = state_emb + (tok - 30) * Esz;
        w   = W_ih + (size_t)g * (2 * Esz) + Esz;
    }

    float acc = 0.f;
    for (int k = lane; k < Esz; k += 32)
        acc += emb[k] * w[k];
    #pragma unroll
    for (int off = 16; off; off >>= 1)
        acc += __shfl_xor_sync(0xFFFFFFFFu, acc, off);

    if (lane == 0) {
        if (tok < 30)
            g_letter_proj[tok * G4 + g] = acc + b_ih[g] + b_hh[g];
        else
            g_state_proj[(tok - 30) * G4 + g] = acc;
    }
}

// ---------------------------------------------------------------------------
// HMMA LSTM step. grid (32, 4) = 128 CTAs, 256 threads (8 warps, 2x4).
// Warp tile M32 x N32. D = Ahi*Bhi + Alo*Bhi + Ahi*Blo (fp32 accum).
// 3-stage cp.async pipeline, one __syncthreads per chunk.
// ---------------------------------------------------------------------------
__global__ void __launch_bounds__(256, 1)
lstm_step_mma(const int* __restrict__ letter_seq,
              const int* __restrict__ state_seq,
              float* __restrict__ out_h,
              float* __restrict__ out_c,
              int s) {
    extern __shared__ char smem[];
    const uint32_t smem_base = smem_u32(smem);

    const int tid = threadIdx.x;
    const int h0  = blockIdx.x * HT;
    const int bm0 = blockIdx.y * BMt;
    const int rbuf = (s & 1) ^ 1;
    const int wbuf = s & 1;

    const int wid = tid >> 5;
    const int l   = tid & 31;
    const int wm  = wid >> 2;         // 0..1
    const int wn  = wid & 3;          // 0..3

    float acc[2][4][4];
    #pragma unroll
    for (int i = 0; i < 2; i++)
        #pragma unroll
        for (int j = 0; j < 4; j++)
            #pragma unroll
            for (int k = 0; k < 4; k++)
                acc[i][j][k] = 0.f;

    if (s > 0) {
        // ---- stage-load constants ----
        const int r  = tid >> 3;                 // 0..31
        const int gq = tid & 7;                  // 16B granule in 128B row
        const uint32_t sw = (uint32_t)((gq ^ (r & 7)) * 16);
        const __nv_bfloat16* hh = g_h_hi[rbuf] + (size_t)(bm0 + r) * Hsz + gq * 8;
        const __nv_bfloat16* hl = g_h_lo[rbuf] + (size_t)(bm0 + r) * Hsz + gq * 8;
        const size_t wrow = (size_t)(h0 + r) * Hsz + gq * 8;

        auto load_stage = [&](int ch) {
            const int k0 = ch * KC;
            const uint32_t sb = smem_base + (uint32_t)(ch % NSTAGE) * STAGE_BYTES;
            cp16(sb + OFF_AHI + r * 128 + sw,        hh + k0);
            cp16(sb + OFF_AHI + (r + 32) * 128 + sw, hh + k0 + 32 * Hsz);
            cp16(sb + OFF_ALO + r * 128 + sw,        hl + k0);
            cp16(sb + OFF_ALO + (r + 32) * 128 + sw, hl + k0 + 32 * Hsz);
            #pragma unroll
            for (int gate = 0; gate < 4; gate++) {
                const size_t off = wrow + (size_t)gate * Hsz * Hsz + k0;
                const uint32_t sn = (uint32_t)(gate * 32 + r) * 128 + sw;
                cp16(sb + OFF_BHI + sn, g_W_hi + off);
                cp16(sb + OFF_BLO + sn, g_W_lo + off);
            }
        };

        // ---- ldmatrix lane constants ----
        const int a_r0 = wm * 32 + (l & 7) + ((l >> 3) & 1) * 8;  // +16 for mf=1
        const int a_kh = l >> 4;
        const int b_n0 = wn * 32 + (l & 7) + (l >> 4) * 8;        // +16 for x=1
        const int b_kh = (l >> 3) & 1;

        load_stage(0); CP_COMMIT();
        load_stage(1); CP_COMMIT();

        for (int ch = 0; ch < NCHUNK; ch++) {
            CP_WAIT1();
            __syncthreads();
            if (ch + 2 < NCHUNK) load_stage(ch + 2);
            CP_COMMIT();

            const uint32_t sb = smem_base + (uint32_t)(ch % NSTAGE) * STAGE_BYTES;
            #pragma unroll
            for (int ks = 0; ks < 4; ks++) {
                const int agq = ks * 2 + a_kh;
                const int bgq = ks * 2 + b_kh;
                uint32_t ah[2][4], al[2][4], bh[2][4], bl[2][4];
                #pragma unroll
                for (int mf = 0; mf < 2; mf++) {
                    int ar = a_r0 + mf * 16;
                    uint32_t arow = (uint32_t)ar * 128
                                  + (uint32_t)((agq ^ (ar & 7)) * 16);
                    ldsm4(sb + OFF_AHI + arow, ah[mf]);
                    ldsm4(sb + OFF_ALO + arow, al[mf]);
                }
                #pragma unroll
                for (int x = 0; x < 2; x++) {
                    int bn = b_n0 + x * 16;
                    uint32_t brow = (uint32_t)bn * 128
                                  + (uint32_t)((bgq ^ (bn & 7)) * 16);
                    ldsm4(sb + OFF_BHI + brow, bh[x]);
                    ldsm4(sb + OFF_BLO + brow, bl[x]);
                }
                // term-major ordering: reuse distance 4 into each acc quad
                #pragma unroll
                for (int mf = 0; mf < 2; mf++)
                    #pragma unroll
                    for (int x = 0; x < 2; x++) {
                        mma16816(acc[mf][x * 2],     ah[mf], &bh[x][0]);
                        mma16816(acc[mf][x * 2 + 1], ah[mf], &bh[x][2]);
                    }
                #pragma unroll
                for (int mf = 0; mf < 2; mf++)
                    #pragma unroll
                    for (int x = 0; x < 2; x++) {
                        mma16816(acc[mf][x * 2],     al[mf], &bh[x][0]);
                        mma16816(acc[mf][x * 2 + 1], al[mf], &bh[x][2]);
                    }
                #pragma unroll
                for (int mf = 0; mf < 2; mf++)
                    #pragma unroll
                    for (int x = 0; x < 2; x++) {
                        mma16816(acc[mf][x * 2],     ah[mf], &bl[x][0]);
                        mma16816(acc[mf][x * 2 + 1], ah[mf], &bl[x][2]);
                    }
            }
        }

        // ---- dump accums to smem D[64][DPITCH] ----
        __syncthreads();
        float* Dsm = (float*)smem;
        #pragma unroll
        for (int mf = 0; mf < 2; mf++)
            #pragma unroll
            for (int nf = 0; nf < 4; nf++) {
                int m = wm * 32 + mf * 16 + (l >> 2);
                int n = wn * 32 + nf * 8 + (l & 3) * 2;
                *(float2*)&Dsm[m * DPITCH + n] =
                    make_float2(acc[mf][nf][0], acc[mf][nf][1]);
                *(float2*)&Dsm[(m + 8) * DPITCH + n] =
                    make_float2(acc[mf][nf][2], acc[mf][nf][3]);
            }
        __syncthreads();
    }

    // ---- fused LSTM cell epilogue ----
    {
        const float* Dsm = (const float*)smem;
        const int m  = tid >> 2;          // 0..63
        const int hq = tid & 3;           // 8-col group
        const int b  = bm0 + m;
        const int lt = letter_seq[b * Ssz + s];
        const int st = state_seq[b * Ssz + s];
        const float* lp = g_letter_proj + (size_t)lt * G4 + h0;
        const float* sp = g_state_proj  + (size_t)st * G4 + h0;
        const size_t base = (size_t)b * (Ssz * Hsz) + (size_t)s * Hsz + h0;
        const size_t cbase = (size_t)b * Hsz + h0;
        const int hl0 = hq * 8;

        float hv[8], cv[8];
        #pragma unroll
        for (int j = 0; j < 8; j++) {
            const int hlc = hl0 + j;
            float pi, pf, pg, po;
            if (s > 0) {
                pi = Dsm[m * DPITCH + 0 * 32 + hlc];
                pf = Dsm[m * DPITCH + 1 * 32 + hlc];
                pg = Dsm[m * DPITCH + 2 * 32 + hlc];
                po = Dsm[m * DPITCH + 3 * 32 + hlc];
            } else {
                pi = pf = pg = po = 0.f;
            }
            pi += lp[hlc]           + sp[hlc];
            pf += lp[Hsz + hlc]     + sp[Hsz + hlc];
            pg += lp[2 * Hsz + hlc] + sp[2 * Hsz + hlc];
            po += lp[3 * Hsz + hlc] + sp[3 * Hsz + hlc];
            float cprev = (s > 0) ? g_c[rbuf][cbase + hlc] : 0.f;
            float c = sigmoidf_(pf) * cprev + sigmoidf_(pi) * tanhf(pg);
            cv[j] = c;
            hv[j] = sigmoidf_(po) * tanhf(c);
        }
        // output-only streams: evict-first so W_hh stays L2-resident
        #pragma unroll
        for (int j = 0; j < 2; j++) {
            stcs4(out_h + base + hl0 + j * 4,
                  make_float4(hv[j*4], hv[j*4+1], hv[j*4+2], hv[j*4+3]));
            stcs4(out_c + base + hl0 + j * 4,
                  make_float4(cv[j*4], cv[j*4+1], cv[j*4+2], cv[j*4+3]));
        }
        // recurrent state (small, re-read next step): normal cached stores
        #pragma unroll
        for (int j = 0; j < 2; j++)
            *(float4*)(g_c[wbuf] + cbase + hl0 + j * 4) =
                make_float4(cv[j*4], cv[j*4+1], cv[j*4+2], cv[j*4+3]);

        __nv_bfloat162 dh[4], dl[4];
        #pragma unroll
        for (int j = 0; j < 4; j++) {
            float x0 = hv[2*j], x1 = hv[2*j+1];
            __nv_bfloat16 b0 = __float2bfloat16(x0);
            __nv_bfloat16 b1 = __float2bfloat16(x1);
            dh[j] = __nv_bfloat162(b0, b1);
            dl[j] = __nv_bfloat162(__float2bfloat16(x0 - __bfloat162float(b0)),
                                   __float2bfloat16(x1 - __bfloat162float(b1)));
        }
        *(uint4*)(g_h_hi[wbuf] + cbase + hl0) = *(const uint4*)dh;
        *(uint4*)(g_h_lo[wbuf] + cbase + hl0) = *(const uint4*)dl;
    }
}

// ---------------------------------------------------------------------------
extern "C" void kernel_launch(void* const* d_in, const int* in_sizes, int n_in,
                              void* d_out, int out_size) {
    const int*   letter_seq = (const int*)d_in[0];
    const int*   state_seq  = (const int*)d_in[1];
    const float* letter_emb = (const float*)d_in[2];
    const float* state_emb  = (const float*)d_in[3];
    const float* W_ih       = (const float*)d_in[4];
    const float* W_hh       = (const float*)d_in[5];
    const float* b_ih       = (const float*)d_in[6];
    const float* b_hh       = (const float*)d_in[7];

    float* out_h = (float*)d_out;
    float* out_c = out_h + (size_t)Bsz * Ssz * Hsz;

    static int smem_set = 0;
    if (!smem_set) {
        cudaFuncSetAttribute(lstm_step_mma,
                             cudaFuncAttributeMaxDynamicSharedMemorySize,
                             SMEM_TOTAL);
        smem_set = 1;
    }

    wsplit_kernel<<<(G4 * Hsz) / (256 * 4), 256>>>(W_hh);
    proj_kernel<<<dim3(G4 / 8, 34), 256>>>(letter_emb, state_emb, W_ih, b_ih, b_hh);

    for (int s = 0; s < Ssz; s++) {
        lstm_step_mma<<<dim3(Hsz / HT, Bsz / BMt), 256, SMEM_TOTAL>>>(
            letter_seq, state_seq, out_h, out_c, s);
    }
}